// round 10
// baseline (speedup 1.0000x reference)
#include <cuda_runtime.h>
#include <cstdint>

#define N_PTS    8192
#define N_SMP    2048
#define BATCH    8
#define CHANNELS 128

// KNN decomposition inside the fused kernel
#define KNN_CTAS_PER_BATCH 32          // 256 queries per CTA
#define KNN_Q_PER_CTA      256
#define CHUNK_PTS          4096

// force 1 CTA/SM (2 x 116KB > 227KB): FPS CTAs never share an SM with KNN
#define FUSED_SMEM_BYTES   (116 * 1024)

// device-global scratch (sanctioned workaround for no-malloc rule)
__device__ int   g_idx[BATCH * N_SMP];                          // FPS sample indices
__device__ float g_allpooled[(size_t)BATCH * CHANNELS * N_PTS]; // pooled feats, ALL points

// ---- packed f32x2 helpers (two independent rn-rounded f32 ops per instr).
// Fallback is two scalar rn ops: bit-identical either way. ----
#if defined(__CUDA_ARCH__) && (__CUDA_ARCH__ >= 1000)
#define HAS_F32X2 1
#else
#define HAS_F32X2 0
#endif

struct P2 { float lo, hi; };

__device__ __forceinline__ P2 pk2(float a, float b) { P2 r; r.lo = a; r.hi = b; return r; }

__device__ __forceinline__ P2 add2(P2 a, P2 b) {
#if HAS_F32X2
    unsigned long long av, bv, rv;
    asm("mov.b64 %0, {%1, %2};" : "=l"(av) : "f"(a.lo), "f"(a.hi));
    asm("mov.b64 %0, {%1, %2};" : "=l"(bv) : "f"(b.lo), "f"(b.hi));
    asm("add.rn.f32x2 %0, %1, %2;" : "=l"(rv) : "l"(av), "l"(bv));
    P2 r;
    asm("mov.b64 {%0, %1}, %2;" : "=f"(r.lo), "=f"(r.hi) : "l"(rv));
    return r;
#else
    P2 r; r.lo = __fadd_rn(a.lo, b.lo); r.hi = __fadd_rn(a.hi, b.hi); return r;
#endif
}

__device__ __forceinline__ P2 sub2(P2 a, P2 b) {
#if HAS_F32X2
    unsigned long long av, bv, rv;
    asm("mov.b64 %0, {%1, %2};" : "=l"(av) : "f"(a.lo), "f"(a.hi));
    asm("mov.b64 %0, {%1, %2};" : "=l"(bv) : "f"(b.lo), "f"(b.hi));
    asm("sub.rn.f32x2 %0, %1, %2;" : "=l"(rv) : "l"(av), "l"(bv));
    P2 r;
    asm("mov.b64 {%0, %1}, %2;" : "=f"(r.lo), "=f"(r.hi) : "l"(rv));
    return r;
#else
    P2 r; r.lo = __fsub_rn(a.lo, b.lo); r.hi = __fsub_rn(a.hi, b.hi); return r;
#endif
}

__device__ __forceinline__ P2 mul2(P2 a, P2 b) {
#if HAS_F32X2
    unsigned long long av, bv, rv;
    asm("mov.b64 %0, {%1, %2};" : "=l"(av) : "f"(a.lo), "f"(a.hi));
    asm("mov.b64 %0, {%1, %2};" : "=l"(bv) : "f"(b.lo), "f"(b.hi));
    asm("mul.rn.f32x2 %0, %1, %2;" : "=l"(rv) : "l"(av), "l"(bv));
    P2 r;
    asm("mov.b64 {%0, %1}, %2;" : "=f"(r.lo), "=f"(r.hi) : "l"(rv));
    return r;
#else
    P2 r; r.lo = __fmul_rn(a.lo, b.lo); r.hi = __fmul_rn(a.hi, b.hi); return r;
#endif
}

// ---------------------------------------------------------------------------
// FPS body: single CTA (1024 threads) per batch, bit-exact selection.
// vs Round 8: the post-barrier combine (LDS + 2 dependent REDUXes per warp)
// is replaced by ONE u64 atomicMax per warp into a double-buffered smem
// slot packed as (iter_tag<<45 | dist_bits<<13 | (8191-idx)):
//   - max on dist_bits (dist>=0 so float bits order as u32)
//   - tie -> max(8191-idx) = min idx  (jnp.argmax first-occurrence)
//   - monotone iter tag makes stale slot contents always lose -> no reset,
//     and BAR ordering makes slot reuse race-free (any post for iter m+2
//     is behind BAR(m+1), which is behind every read of iter m).
// ---------------------------------------------------------------------------
__device__ void fps_body(const float* __restrict__ pos, char* smem, int b)
{
    float2* xy = (float2*)smem;                    // [8192]  64 KB
    float*  zs = (float*)(smem + N_PTS * 8);       // [8192]  32 KB
    __shared__ unsigned long long s_best[2];

    const int t = threadIdx.x;
    const int lane = t & 31;
    const float* p = pos + (size_t)b * 3 * N_PTS;

    // slot s owns point j = t + s*1024; pair q packs slots (2q, 2q+1)
    P2 x2[4], y2[4], z2[4];
    float dist[8];
    {
        float xv[8], yv[8], zv[8];
#pragma unroll
        for (int s = 0; s < 8; s++) {
            int j = t + (s << 10);
            xv[s] = p[j];
            yv[s] = p[N_PTS + j];
            zv[s] = p[2 * N_PTS + j];
            xy[j] = make_float2(xv[s], yv[s]);
            zs[j] = zv[s];
            dist[s] = 1e10f;   // reference init 10000000000.0
        }
#pragma unroll
        for (int q = 0; q < 4; q++) {
            x2[q] = pk2(xv[2 * q], xv[2 * q + 1]);
            y2[q] = pk2(yv[2 * q], yv[2 * q + 1]);
            z2[q] = pk2(zv[2 * q], zv[2 * q + 1]);
        }
    }
    if (t == 0) { s_best[0] = 0ull; s_best[1] = 0ull; }
    __syncthreads();

    int far = 0;
    int* idxout = g_idx + b * N_SMP;

    for (int m = 0; m < N_SMP; m++) {
        float2 cxy = xy[far];
        float  cz  = zs[far];
        if (t == 0) idxout[m] = far;   // scan emits `farthest` at step entry
        P2 cxx = pk2(cxy.x, cxy.x);
        P2 cyy = pk2(cxy.y, cxy.y);
        P2 czz = pk2(cz, cz);

        // dist >= 0: float bits order as u32; strict '>' in ascending
        // slot order keeps first occurrence (jnp.argmax semantics).
        unsigned bestb = 0u;
        int bidx = t;
#pragma unroll
        for (int q = 0; q < 4; q++) {
            P2 dx = sub2(x2[q], cxx);
            P2 dy = sub2(y2[q], cyy);
            P2 dz = sub2(z2[q], czz);
            P2 xx = mul2(dx, dx);
            P2 yy = mul2(dy, dy);
            P2 zz = mul2(dz, dz);
            P2 d2 = add2(add2(xx, yy), zz);   // ((xx+yy)+zz), each rn
            float nlo = fminf(dist[2 * q], d2.lo);
            float nhi = fminf(dist[2 * q + 1], d2.hi);
            dist[2 * q]     = nlo;
            dist[2 * q + 1] = nhi;
            unsigned blo = __float_as_uint(nlo);
            if (blo > bestb) { bestb = blo; bidx = t + (q << 11); }
            unsigned bhi = __float_as_uint(nhi);
            if (bhi > bestb) { bestb = bhi; bidx = t + (q << 11) + 1024; }
        }

        // warp argmax via REDUX: max value bits, min idx among matches
        unsigned wmax = __reduce_max_sync(0xffffffffu, bestb);
        unsigned cand = (bestb == wmax) ? (unsigned)bidx : 0xffffffffu;
        unsigned widx = __reduce_min_sync(0xffffffffu, cand);

        const int buf = m & 1;
        if (lane == 0) {
            unsigned long long pkv = ((unsigned long long)(unsigned)m << 45)
                                   | ((unsigned long long)wmax << 13)
                                   | (unsigned long long)(8191u - widx);
            atomicMax(&s_best[buf], pkv);
        }
        __syncthreads();

        unsigned long long v = s_best[buf];
        far = 8191 - (int)((unsigned)v & 0x1fffu);
    }
}

// ---------------------------------------------------------------------------
// All-pairs KNN body: 4-NN + channel max-pool for EVERY input point
// (sampled queries are input points, so query m's row == point idx[m]'s row
// under the reference's own dist formula). Unchanged from Round 7/8.
// ---------------------------------------------------------------------------
__device__ void allknn_body(const float* __restrict__ feats,
                            const float* __restrict__ pos,
                            char* smem, int cta)
{
    float4* tile = (float4*)smem;      // [4096] = 64 KB of the alloc

    const int b    = cta / KNN_CTAS_PER_BATCH;
    const int qblk = cta % KNN_CTAS_PER_BATCH;
    const int t    = threadIdx.x;
    const int part = t & 3;
    const int q    = qblk * KNN_Q_PER_CTA + (t >> 2);   // 0..8191

    const float* p = pos + (size_t)b * 3 * N_PTS;
    float sx = p[q];
    float sy = p[N_PTS + q];
    float sz = p[2 * N_PTS + q];
    float s2 = __fadd_rn(__fadd_rn(__fmul_rn(sx, sx), __fmul_rn(sy, sy)),
                         __fmul_rn(sz, sz));

    const float INF = __int_as_float(0x7f800000);
    float d0 = INF, d1 = INF, d2 = INF, d3 = INF;
    int   i0 = 0x7fffffff, i1 = 0x7fffffff, i2 = 0x7fffffff, i3 = 0x7fffffff;

    for (int chunk = 0; chunk < N_PTS / CHUNK_PTS; chunk++) {
        const int base = chunk * CHUNK_PTS;
        __syncthreads();   // previous chunk fully consumed before overwrite
        for (int j = t; j < CHUNK_PTS; j += 1024) {
            int g = base + j;
            float px = p[g];
            float py = p[N_PTS + g];
            float pz = p[2 * N_PTS + g];
            float p2 = __fadd_rn(__fadd_rn(__fmul_rn(px, px), __fmul_rn(py, py)),
                                 __fmul_rn(pz, pz));
            tile[j] = make_float4(px, py, pz, p2);
        }
        __syncthreads();

        // ascending global idx within a part -> '<' keeps first occurrence
#pragma unroll 4
        for (int i = 0; i < CHUNK_PTS / 4; i++) {
            int e = (i << 2) + part;
            float4 pt = tile[e];
            float cross = __fadd_rn(__fadd_rn(__fmul_rn(sx, pt.x), __fmul_rn(sy, pt.y)),
                                    __fmul_rn(sz, pt.z));
            float dv = __fsub_rn(__fadd_rn(s2, pt.w), __fmul_rn(2.0f, cross));
            if (dv < d3) {
                int j = base + e;
                if (dv < d2) {
                    d3 = d2; i3 = i2;
                    if (dv < d1) {
                        d2 = d1; i2 = i1;
                        if (dv < d0) { d1 = d0; i1 = i0; d0 = dv; i0 = j; }
                        else         { d1 = dv; i1 = j; }
                    } else { d2 = dv; i2 = j; }
                } else { d3 = dv; i3 = j; }
            }
        }
    }

    // merge 4 per-part sorted lists: 4 rounds of (d, idx)-lexicographic min
    int mi[4];
#pragma unroll
    for (int r = 0; r < 4; r++) {
        float hd = d0;
        int   hi = i0;
#pragma unroll
        for (int off = 1; off < 4; off <<= 1) {
            float od = __shfl_xor_sync(0xffffffffu, hd, off, 4);
            int   oi = __shfl_xor_sync(0xffffffffu, hi, off, 4);
            if (od < hd || (od == hd && oi < hi)) { hd = od; hi = oi; }
        }
        mi[r] = hi;
        if (hi == i0) {   // global indices unique -> exact pop test
            d0 = d1; i0 = i1;
            d1 = d2; i1 = i2;
            d2 = d3; i2 = i3;
            d3 = INF; i3 = 0x7fffffff;
        }
    }

    // each part max-pools its own 32 channels into the all-points buffer
    const float* f0 = feats + (size_t)b * CHANNELS * N_PTS;
    float* gp = g_allpooled + (size_t)b * CHANNELS * N_PTS + q;
#pragma unroll 4
    for (int cc = 0; cc < CHANNELS / 4; cc++) {
        int c = part * (CHANNELS / 4) + cc;
        const float* fc = f0 + (size_t)c * N_PTS;
        float v = fmaxf(fmaxf(__ldg(fc + mi[0]), __ldg(fc + mi[1])),
                        fmaxf(__ldg(fc + mi[2]), __ldg(fc + mi[3])));
        gp[(size_t)c * N_PTS] = v;
    }
}

// ---------------------------------------------------------------------------
// Fused kernel: bids 0..7 = FPS (one per batch); bids 8..263 = all-pairs
// KNN (concurrent on the other SMs, finishes well inside the FPS window).
// 116 KB dynamic smem forces 1 CTA/SM -> FPS never shares an SM with KNN.
// ---------------------------------------------------------------------------
__global__ void __launch_bounds__(1024, 1)
fused_kernel(const float* __restrict__ feats,
             const float* __restrict__ pos)
{
    extern __shared__ char smem[];
    if (blockIdx.x < BATCH) {
        fps_body(pos, smem, blockIdx.x);
    } else {
        allknn_body(feats, pos, smem, blockIdx.x - BATCH);
    }
}

// ---------------------------------------------------------------------------
// Epilogue: pooled[b,c,m] = allpooled[b,c, idx[b,m]]  (L2-hot gather) and
// sampled[b,r,m] = pos[b,r, idx[b,m]]  (verbatim coord copy, bit-identical
// to what the FPS loop used to store).
// ---------------------------------------------------------------------------
#define POOL_ELEMS (BATCH * CHANNELS * N_SMP)      // 2,097,152
#define SMP_ELEMS  (BATCH * 3 * N_SMP)             // 49,152

__global__ void __launch_bounds__(256)
gather_kernel(const float* __restrict__ pos,
              float* __restrict__ pooled,
              float* __restrict__ sampled)
{
    int gid = blockIdx.x * 256 + threadIdx.x;
    if (gid < POOL_ELEMS) {
        int m  = gid & (N_SMP - 1);
        int bc = gid >> 11;                        // b*128 + c
        int b  = bc >> 7;
        int i  = g_idx[b * N_SMP + m];
        pooled[gid] = g_allpooled[(size_t)bc * N_PTS + i];
    } else {
        int sid = gid - POOL_ELEMS;
        int m = sid & (N_SMP - 1);
        int br = sid >> 11;                        // b*3 + r
        int b  = br / 3;
        int r  = br - 3 * b;
        int i  = g_idx[b * N_SMP + m];
        sampled[sid] = pos[((size_t)b * 3 + r) * N_PTS + i];
    }
}

// ---------------------------------------------------------------------------
// Launch
// ---------------------------------------------------------------------------
extern "C" void kernel_launch(void* const* d_in, const int* in_sizes, int n_in,
                              void* d_out, int out_size)
{
    const float* feats = (const float*)d_in[0];   // (8,128,8192)
    const float* pos   = (const float*)d_in[1];   // (8,3,8192)

    float* pooled  = (float*)d_out;                                    // (8,128,2048)
    float* sampled = (float*)d_out + (size_t)BATCH * CHANNELS * N_SMP; // (8,3,2048)

    cudaFuncSetAttribute(fused_kernel,
                         cudaFuncAttributeMaxDynamicSharedMemorySize,
                         FUSED_SMEM_BYTES);

    const int n_ctas = BATCH + BATCH * KNN_CTAS_PER_BATCH;   // 264
    fused_kernel<<<n_ctas, 1024, FUSED_SMEM_BYTES>>>(feats, pos);

    const int tot = POOL_ELEMS + SMP_ELEMS;                  // 2,146,304
    gather_kernel<<<tot / 256, 256>>>(pos, pooled, sampled);
}

// round 13
// speedup vs baseline: 1.3848x; 1.3848x over previous
#include <cuda_runtime.h>
#include <cstdint>

// PointMaxPool fused pipeline, revision r13 (functionally identical to r11).
#define N_PTS    8192
#define N_SMP    2048
#define BATCH    8
#define CHANNELS 128

// KNN decomposition inside the fused kernel
#define KNN_CTAS_PER_BATCH 32          // 256 queries per CTA
#define KNN_Q_PER_CTA      256
#define CHUNK_PTS          4096

// force 1 CTA/SM (2 x 116KB > 227KB): FPS CTAs never share an SM with KNN
#define FUSED_SMEM_BYTES   (116 * 1024)

// device-global scratch (sanctioned workaround for no-malloc rule)
__device__ int   g_idx[BATCH * N_SMP];                          // FPS sample indices
__device__ float g_allpooled[(size_t)BATCH * CHANNELS * N_PTS]; // pooled feats, ALL points

// ---- packed f32x2 helpers (two independent rn-rounded f32 ops per instr).
// Fallback is two scalar rn ops: bit-identical either way. ----
#if defined(__CUDA_ARCH__) && (__CUDA_ARCH__ >= 1000)
#define HAS_F32X2 1
#else
#define HAS_F32X2 0
#endif

struct P2 { float lo, hi; };

__device__ __forceinline__ P2 pk2(float a, float b) { P2 r; r.lo = a; r.hi = b; return r; }

__device__ __forceinline__ P2 add2(P2 a, P2 b) {
#if HAS_F32X2
    unsigned long long av, bv, rv;
    asm("mov.b64 %0, {%1, %2};" : "=l"(av) : "f"(a.lo), "f"(a.hi));
    asm("mov.b64 %0, {%1, %2};" : "=l"(bv) : "f"(b.lo), "f"(b.hi));
    asm("add.rn.f32x2 %0, %1, %2;" : "=l"(rv) : "l"(av), "l"(bv));
    P2 r;
    asm("mov.b64 {%0, %1}, %2;" : "=f"(r.lo), "=f"(r.hi) : "l"(rv));
    return r;
#else
    P2 r; r.lo = __fadd_rn(a.lo, b.lo); r.hi = __fadd_rn(a.hi, b.hi); return r;
#endif
}

__device__ __forceinline__ P2 sub2(P2 a, P2 b) {
#if HAS_F32X2
    unsigned long long av, bv, rv;
    asm("mov.b64 %0, {%1, %2};" : "=l"(av) : "f"(a.lo), "f"(a.hi));
    asm("mov.b64 %0, {%1, %2};" : "=l"(bv) : "f"(b.lo), "f"(b.hi));
    asm("sub.rn.f32x2 %0, %1, %2;" : "=l"(rv) : "l"(av), "l"(bv));
    P2 r;
    asm("mov.b64 {%0, %1}, %2;" : "=f"(r.lo), "=f"(r.hi) : "l"(rv));
    return r;
#else
    P2 r; r.lo = __fsub_rn(a.lo, b.lo); r.hi = __fsub_rn(a.hi, b.hi); return r;
#endif
}

__device__ __forceinline__ P2 mul2(P2 a, P2 b) {
#if HAS_F32X2
    unsigned long long av, bv, rv;
    asm("mov.b64 %0, {%1, %2};" : "=l"(av) : "f"(a.lo), "f"(a.hi));
    asm("mov.b64 %0, {%1, %2};" : "=l"(bv) : "f"(b.lo), "f"(b.hi));
    asm("mul.rn.f32x2 %0, %1, %2;" : "=l"(rv) : "l"(av), "l"(bv));
    P2 r;
    asm("mov.b64 {%0, %1}, %2;" : "=f"(r.lo), "=f"(r.hi) : "l"(rv));
    return r;
#else
    P2 r; r.lo = __fmul_rn(a.lo, b.lo); r.hi = __fmul_rn(a.hi, b.hi); return r;
#endif
}

// ---------------------------------------------------------------------------
// FPS body: single CTA (1024 threads) per batch, bit-exact selection.
// Tail = Round-8 proven scheme: warp REDUX -> u64 STS (double-buffered) ->
// one BAR -> every warp LDS.64 + dual REDUX over the 32 candidates.
// No per-point index bookkeeping inside the update loop: after the packed
// update, a 7-op fmax tree gives the per-thread max, warp REDUX gives wmax,
// and the owning index is recovered by a descending equality chain over the
// 8 slots (bit-equality == value-equality for these non-negative floats;
// descending s -> smallest idx wins on ties, matching jnp.argmax
// first-occurrence). Lanes with no match keep cand=0xffffffff.
// ---------------------------------------------------------------------------
__device__ void fps_body(const float* __restrict__ pos, char* smem, int b)
{
    float2* xy = (float2*)smem;                    // [8192]  64 KB
    float*  zs = (float*)(smem + N_PTS * 8);       // [8192]  32 KB
    __shared__ unsigned long long s_cand[2][32];   // (valbits<<32)|idx

    const int t = threadIdx.x;
    const int lane = t & 31;
    const int warp = t >> 5;
    const float* p = pos + (size_t)b * 3 * N_PTS;

    // slot s owns point j = t + s*1024; pair q packs slots (2q, 2q+1)
    P2 x2[4], y2[4], z2[4];
    float dist[8];
    {
        float xv[8], yv[8], zv[8];
#pragma unroll
        for (int s = 0; s < 8; s++) {
            int j = t + (s << 10);
            xv[s] = p[j];
            yv[s] = p[N_PTS + j];
            zv[s] = p[2 * N_PTS + j];
            xy[j] = make_float2(xv[s], yv[s]);
            zs[j] = zv[s];
            dist[s] = 1e10f;   // reference init 10000000000.0
        }
#pragma unroll
        for (int q = 0; q < 4; q++) {
            x2[q] = pk2(xv[2 * q], xv[2 * q + 1]);
            y2[q] = pk2(yv[2 * q], yv[2 * q + 1]);
            z2[q] = pk2(zv[2 * q], zv[2 * q + 1]);
        }
    }
    __syncthreads();

    int far = 0;
    int buf = 0;
    int* idxout = g_idx + b * N_SMP;

    for (int m = 0; m < N_SMP; m++) {
        float2 cxy = xy[far];
        float  cz  = zs[far];
        if (t == 0) idxout[m] = far;   // scan emits `farthest` at step entry
        P2 cxx = pk2(cxy.x, cxy.x);
        P2 cyy = pk2(cxy.y, cxy.y);
        P2 czz = pk2(cz, cz);

        // pure packed distance update (no index tracking in the loop)
#pragma unroll
        for (int q = 0; q < 4; q++) {
            P2 dx = sub2(x2[q], cxx);
            P2 dy = sub2(y2[q], cyy);
            P2 dz = sub2(z2[q], czz);
            P2 xx = mul2(dx, dx);
            P2 yy = mul2(dy, dy);
            P2 zz = mul2(dz, dz);
            P2 d2 = add2(add2(xx, yy), zz);   // ((xx+yy)+zz), each rn
            dist[2 * q]     = fminf(dist[2 * q],     d2.lo);
            dist[2 * q + 1] = fminf(dist[2 * q + 1], d2.hi);
        }

        // per-thread max via 7-op tree
        float t01 = fmaxf(dist[0], dist[1]);
        float t23 = fmaxf(dist[2], dist[3]);
        float t45 = fmaxf(dist[4], dist[5]);
        float t67 = fmaxf(dist[6], dist[7]);
        float tmax = fmaxf(fmaxf(t01, t23), fmaxf(t45, t67));
        unsigned bestb = __float_as_uint(tmax);

        // warp max (dist >= 0 so float bits order as u32)
        unsigned wmax = __reduce_max_sync(0xffffffffu, bestb);
        float wm = __uint_as_float(wmax);

        // recover owning index: descending s, overwrite-on-equal ->
        // smallest matching slot (= smallest global idx for this lane)
        unsigned cand = 0xffffffffu;
#pragma unroll
        for (int s = 7; s >= 0; s--) {
            if (dist[s] == wm) cand = (unsigned)(t + (s << 10));
        }
        unsigned widx = __reduce_min_sync(0xffffffffu, cand);

        if (lane == 0)
            s_cand[buf][warp] = ((unsigned long long)wmax << 32) | widx;
        __syncthreads();

        // every warp redundantly combines the 32 candidates (double-buffered)
        unsigned long long c64 = s_cand[buf][lane];
        unsigned v = (unsigned)(c64 >> 32);
        unsigned i = (unsigned)c64;
        unsigned gmax = __reduce_max_sync(0xffffffffu, v);
        unsigned gc   = (v == gmax) ? i : 0xffffffffu;
        far = (int)__reduce_min_sync(0xffffffffu, gc);
        buf ^= 1;
    }
}

// ---------------------------------------------------------------------------
// All-pairs KNN body: 4-NN + channel max-pool for EVERY input point
// (sampled queries are input points, so query m's row == point idx[m]'s row
// under the reference's own dist formula). Unchanged from Rounds 7/8.
// ---------------------------------------------------------------------------
__device__ void allknn_body(const float* __restrict__ feats,
                            const float* __restrict__ pos,
                            char* smem, int cta)
{
    float4* tile = (float4*)smem;      // [4096] = 64 KB of the alloc

    const int b    = cta / KNN_CTAS_PER_BATCH;
    const int qblk = cta % KNN_CTAS_PER_BATCH;
    const int t    = threadIdx.x;
    const int part = t & 3;
    const int q    = qblk * KNN_Q_PER_CTA + (t >> 2);   // 0..8191

    const float* p = pos + (size_t)b * 3 * N_PTS;
    float sx = p[q];
    float sy = p[N_PTS + q];
    float sz = p[2 * N_PTS + q];
    float s2 = __fadd_rn(__fadd_rn(__fmul_rn(sx, sx), __fmul_rn(sy, sy)),
                         __fmul_rn(sz, sz));

    const float INF = __int_as_float(0x7f800000);
    float d0 = INF, d1 = INF, d2 = INF, d3 = INF;
    int   i0 = 0x7fffffff, i1 = 0x7fffffff, i2 = 0x7fffffff, i3 = 0x7fffffff;

    for (int chunk = 0; chunk < N_PTS / CHUNK_PTS; chunk++) {
        const int base = chunk * CHUNK_PTS;
        __syncthreads();   // previous chunk fully consumed before overwrite
        for (int j = t; j < CHUNK_PTS; j += 1024) {
            int g = base + j;
            float px = p[g];
            float py = p[N_PTS + g];
            float pz = p[2 * N_PTS + g];
            float p2 = __fadd_rn(__fadd_rn(__fmul_rn(px, px), __fmul_rn(py, py)),
                                 __fmul_rn(pz, pz));
            tile[j] = make_float4(px, py, pz, p2);
        }
        __syncthreads();

        // ascending global idx within a part -> '<' keeps first occurrence
#pragma unroll 4
        for (int i = 0; i < CHUNK_PTS / 4; i++) {
            int e = (i << 2) + part;
            float4 pt = tile[e];
            float cross = __fadd_rn(__fadd_rn(__fmul_rn(sx, pt.x), __fmul_rn(sy, pt.y)),
                                    __fmul_rn(sz, pt.z));
            float dv = __fsub_rn(__fadd_rn(s2, pt.w), __fmul_rn(2.0f, cross));
            if (dv < d3) {
                int j = base + e;
                if (dv < d2) {
                    d3 = d2; i3 = i2;
                    if (dv < d1) {
                        d2 = d1; i2 = i1;
                        if (dv < d0) { d1 = d0; i1 = i0; d0 = dv; i0 = j; }
                        else         { d1 = dv; i1 = j; }
                    } else { d2 = dv; i2 = j; }
                } else { d3 = dv; i3 = j; }
            }
        }
    }

    // merge 4 per-part sorted lists: 4 rounds of (d, idx)-lexicographic min
    int mi[4];
#pragma unroll
    for (int r = 0; r < 4; r++) {
        float hd = d0;
        int   hi = i0;
#pragma unroll
        for (int off = 1; off < 4; off <<= 1) {
            float od = __shfl_xor_sync(0xffffffffu, hd, off, 4);
            int   oi = __shfl_xor_sync(0xffffffffu, hi, off, 4);
            if (od < hd || (od == hd && oi < hi)) { hd = od; hi = oi; }
        }
        mi[r] = hi;
        if (hi == i0) {   // global indices unique -> exact pop test
            d0 = d1; i0 = i1;
            d1 = d2; i1 = i2;
            d2 = d3; i2 = i3;
            d3 = INF; i3 = 0x7fffffff;
        }
    }

    // each part max-pools its own 32 channels into the all-points buffer
    const float* f0 = feats + (size_t)b * CHANNELS * N_PTS;
    float* gp = g_allpooled + (size_t)b * CHANNELS * N_PTS + q;
#pragma unroll 4
    for (int cc = 0; cc < CHANNELS / 4; cc++) {
        int c = part * (CHANNELS / 4) + cc;
        const float* fc = f0 + (size_t)c * N_PTS;
        float v = fmaxf(fmaxf(__ldg(fc + mi[0]), __ldg(fc + mi[1])),
                        fmaxf(__ldg(fc + mi[2]), __ldg(fc + mi[3])));
        gp[(size_t)c * N_PTS] = v;
    }
}

// ---------------------------------------------------------------------------
// Fused kernel: bids 0..7 = FPS (one per batch); bids 8..263 = all-pairs
// KNN (concurrent on the other SMs, finishes well inside the FPS window).
// 116 KB dynamic smem forces 1 CTA/SM -> FPS never shares an SM with KNN.
// ---------------------------------------------------------------------------
__global__ void __launch_bounds__(1024, 1)
fused_kernel(const float* __restrict__ feats,
             const float* __restrict__ pos)
{
    extern __shared__ char smem[];
    if (blockIdx.x < BATCH) {
        fps_body(pos, smem, blockIdx.x);
    } else {
        allknn_body(feats, pos, smem, blockIdx.x - BATCH);
    }
}

// ---------------------------------------------------------------------------
// Epilogue: pooled[b,c,m] = allpooled[b,c, idx[b,m]]  (L2-hot gather) and
// sampled[b,r,m] = pos[b,r, idx[b,m]]  (verbatim coord copy, bit-identical
// to what the FPS loop used to store).
// ---------------------------------------------------------------------------
#define POOL_ELEMS (BATCH * CHANNELS * N_SMP)      // 2,097,152
#define SMP_ELEMS  (BATCH * 3 * N_SMP)             // 49,152

__global__ void __launch_bounds__(256)
gather_kernel(const float* __restrict__ pos,
              float* __restrict__ pooled,
              float* __restrict__ sampled)
{
    int gid = blockIdx.x * 256 + threadIdx.x;
    if (gid < POOL_ELEMS) {
        int m  = gid & (N_SMP - 1);
        int bc = gid >> 11;                        // b*128 + c
        int b  = bc >> 7;
        int i  = g_idx[b * N_SMP + m];
        pooled[gid] = g_allpooled[(size_t)bc * N_PTS + i];
    } else {
        int sid = gid - POOL_ELEMS;
        int m = sid & (N_SMP - 1);
        int br = sid >> 11;                        // b*3 + r
        int b  = br / 3;
        int r  = br - 3 * b;
        int i  = g_idx[b * N_SMP + m];
        sampled[sid] = pos[((size_t)b * 3 + r) * N_PTS + i];
    }
}

// ---------------------------------------------------------------------------
// Launch
// ---------------------------------------------------------------------------
extern "C" void kernel_launch(void* const* d_in, const int* in_sizes, int n_in,
                              void* d_out, int out_size)
{
    const float* feats = (const float*)d_in[0];   // (8,128,8192)
    const float* pos   = (const float*)d_in[1];   // (8,3,8192)

    float* pooled  = (float*)d_out;                                    // (8,128,2048)
    float* sampled = (float*)d_out + (size_t)BATCH * CHANNELS * N_SMP; // (8,3,2048)

    cudaFuncSetAttribute(fused_kernel,
                         cudaFuncAttributeMaxDynamicSharedMemorySize,
                         FUSED_SMEM_BYTES);

    const int n_ctas = BATCH + BATCH * KNN_CTAS_PER_BATCH;   // 264
    fused_kernel<<<n_ctas, 1024, FUSED_SMEM_BYTES>>>(feats, pos);

    const int tot = POOL_ELEMS + SMP_ELEMS;                  // 2,146,304
    gather_kernel<<<tot / 256, 256>>>(pos, pooled, sampled);
}